// round 1
// baseline (speedup 1.0000x reference)
#include <cuda_runtime.h>
#include <cuda_bf16.h>
#include <math.h>

// ---------------------------------------------------------------------------
// GraphSAGE fraud detector, fp32.
// Pipeline per launch:
//   init -> histogram(deg) -> scan(row_start,cursor) -> scatter(src sorted by dst)
//   3 x [ aggregate(mean over in-edges) ; fused dual-GEMM (+BN+ReLU for L0,L1) ]
//   column-sum reduce -> head MLP -> sigmoid scalar
// ---------------------------------------------------------------------------

#define MAXN 100000
#define MAXE 1600000
#define F 64

__device__ int   g_deg[MAXN];
__device__ int   g_rowstart[MAXN];
__device__ int   g_cursor[MAXN];
__device__ int   g_srcs[MAXE];
__device__ float g_aggr[(size_t)MAXN * F];
__device__ float g_bufA[(size_t)MAXN * F];
__device__ float g_bufB[(size_t)MAXN * F];
__device__ float g_colsum[F];

// ---------------------------------------------------------------------------
__global__ void init_kernel(int nNodes) {
    int i = blockIdx.x * blockDim.x + threadIdx.x;
    if (i < nNodes) g_deg[i] = 0;
    if (i < F) g_colsum[i] = 0.f;
}

__global__ void hist_kernel(const int* __restrict__ dst, int E) {
    int e = blockIdx.x * blockDim.x + threadIdx.x;
    if (e < E) atomicAdd(&g_deg[dst[e]], 1);
}

// single-block exclusive scan of degrees -> row_start + cursor copy
__global__ void scan_kernel(int nNodes) {
    __shared__ int sh[1024];
    int t = threadIdx.x;
    int ch = (nNodes + 1023) >> 10;
    int b = t * ch;
    int e = min(b + ch, nNodes);
    int local = 0;
    for (int i = b; i < e; ++i) local += g_deg[i];
    sh[t] = local;
    __syncthreads();
    for (int off = 1; off < 1024; off <<= 1) {
        int v = (t >= off) ? sh[t - off] : 0;
        __syncthreads();
        sh[t] += v;
        __syncthreads();
    }
    int run = sh[t] - local;  // exclusive prefix
    for (int i = b; i < e; ++i) {
        g_rowstart[i] = run;
        g_cursor[i] = run;
        run += g_deg[i];
    }
}

__global__ void scatter_kernel(const int* __restrict__ src,
                               const int* __restrict__ dst, int E) {
    int e = blockIdx.x * blockDim.x + threadIdx.x;
    if (e < E) {
        int d = dst[e];
        int p = atomicAdd(&g_cursor[d], 1);
        g_srcs[p] = src[e];
    }
}

// ---------------------------------------------------------------------------
// Mean aggregation: one warp per destination node, lane handles 2 features.
__device__ __forceinline__ float2 ld_feat2(const float* __restrict__ h, int s, int lane) {
    return __ldg((const float2*)(h + (size_t)s * F) + lane);
}

__global__ void __launch_bounds__(256) aggregate_kernel(
    const float* __restrict__ hin, int nNodes) {
    int gw = (blockIdx.x * blockDim.x + threadIdx.x) >> 5;
    int lane = threadIdx.x & 31;
    if (gw >= nNodes) return;
    int start = g_rowstart[gw];
    int deg = g_deg[gw];
    float ax = 0.f, ay = 0.f;
    int i = 0;
    for (; i + 4 <= deg; i += 4) {
        int s0 = __ldg(&g_srcs[start + i + 0]);
        int s1 = __ldg(&g_srcs[start + i + 1]);
        int s2 = __ldg(&g_srcs[start + i + 2]);
        int s3 = __ldg(&g_srcs[start + i + 3]);
        float2 t0 = ld_feat2(hin, s0, lane);
        float2 t1 = ld_feat2(hin, s1, lane);
        float2 t2 = ld_feat2(hin, s2, lane);
        float2 t3 = ld_feat2(hin, s3, lane);
        ax += t0.x + t1.x + t2.x + t3.x;
        ay += t0.y + t1.y + t2.y + t3.y;
    }
    for (; i < deg; ++i) {
        int s = __ldg(&g_srcs[start + i]);
        float2 t = ld_feat2(hin, s, lane);
        ax += t.x;
        ay += t.y;
    }
    float inv = deg > 0 ? 1.0f / (float)deg : 0.f;
    ((float2*)(g_aggr + (size_t)gw * F))[lane] = make_float2(ax * inv, ay * inv);
}

// ---------------------------------------------------------------------------
// Fused dual GEMM: out[r][j] = sum_k aggr[r][k]*Wl[j][k] + sum_k H[r][k]*Wr[j][k]
// then (BN_RELU): out = relu(out*scale[j] + shift[j])   (bias folded into shift)
// else: out = raw acc (bias deferred to head via column means)
template <bool BN_RELU>
__global__ void __launch_bounds__(256, 2) gemm_kernel(
    const float* __restrict__ H,
    const float* __restrict__ wl, const float* __restrict__ wr,
    const float* __restrict__ bl,
    const float* __restrict__ gn, const float* __restrict__ be,
    const float* __restrict__ mn, const float* __restrict__ vr,
    float* __restrict__ out, int nNodes) {
    __shared__ float Ws[F][2 * F];  // [j][k], k<64 = Wl, k>=64 = Wr
    __shared__ float s_scale[F];
    __shared__ float s_shift[F];

    int tid = threadIdx.x;
    const float4* wl4 = (const float4*)wl;
    const float4* wr4 = (const float4*)wr;
    for (int i = tid; i < 1024; i += 256) {  // 64*64/4 float4 per matrix
        int j = i >> 4;
        int kc = (i & 15) << 2;
        float4 a = __ldg(wl4 + i);
        float4 b = __ldg(wr4 + i);
        *(float4*)&Ws[j][kc] = a;
        *(float4*)&Ws[j][64 + kc] = b;
    }
    if (BN_RELU && tid < F) {
        float sc = __ldg(&gn[tid]) * rsqrtf(__ldg(&vr[tid]) + 1e-5f);
        s_scale[tid] = sc;
        s_shift[tid] = (__ldg(&bl[tid]) - __ldg(&mn[tid])) * sc + __ldg(&be[tid]);
    }
    __syncthreads();

    int row = blockIdx.x * 256 + tid;
    float acc[F];
#pragma unroll
    for (int j = 0; j < F; ++j) acc[j] = 0.f;

    if (row < nNodes) {
        const float4* a4 = (const float4*)(g_aggr + (size_t)row * F);
        const float4* h4 = (const float4*)(H + (size_t)row * F);
#pragma unroll 1
        for (int kk = 0; kk < 8; ++kk) {
            const float4* sp = (kk < 4) ? a4 : h4;
            int base = (kk & 3) * 4;
            float4 v0 = __ldg(sp + base + 0);
            float4 v1 = __ldg(sp + base + 1);
            float4 v2 = __ldg(sp + base + 2);
            float4 v3 = __ldg(sp + base + 3);
            float a[16] = {v0.x, v0.y, v0.z, v0.w, v1.x, v1.y, v1.z, v1.w,
                           v2.x, v2.y, v2.z, v2.w, v3.x, v3.y, v3.z, v3.w};
            int kb = kk * 16;
#pragma unroll
            for (int j = 0; j < F; ++j) {
                const float* wp = &Ws[j][kb];
#pragma unroll
                for (int k = 0; k < 16; ++k) acc[j] = fmaf(a[k], wp[k], acc[j]);
            }
        }
        float* orow = out + (size_t)row * F;
#pragma unroll
        for (int j = 0; j < F; j += 4) {
            float4 o;
            if (BN_RELU) {
                o.x = fmaxf(acc[j + 0] * s_scale[j + 0] + s_shift[j + 0], 0.f);
                o.y = fmaxf(acc[j + 1] * s_scale[j + 1] + s_shift[j + 1], 0.f);
                o.z = fmaxf(acc[j + 2] * s_scale[j + 2] + s_shift[j + 2], 0.f);
                o.w = fmaxf(acc[j + 3] * s_scale[j + 3] + s_shift[j + 3], 0.f);
            } else {
                o.x = acc[j + 0];
                o.y = acc[j + 1];
                o.z = acc[j + 2];
                o.w = acc[j + 3];
            }
            *(float4*)&orow[j] = o;
        }
    }
}

// ---------------------------------------------------------------------------
// Column sums of final layer output (bias deferred to head kernel).
__global__ void colsum_kernel(const float* __restrict__ hin, int nNodes) {
    int t = blockIdx.x * blockDim.x + threadIdx.x;
    int col = t & 63;
    int r = t >> 6;
    int stride = (gridDim.x * blockDim.x) >> 6;
    float s = 0.f;
    for (; r < nNodes; r += stride) s += __ldg(&hin[(size_t)r * F + col]);
    atomicAdd(&g_colsum[col], s);
}

// head: mean -> Linear(64,64)+ReLU -> Linear(64,1) -> sigmoid
__global__ void head_kernel(const float* __restrict__ bl2,
                            const float* __restrict__ cw1,
                            const float* __restrict__ cb1,
                            const float* __restrict__ cw2,
                            const float* __restrict__ cb2,
                            float* __restrict__ outp, int nNodes) {
    __shared__ float mean[F];
    __shared__ float z[F];
    int t = threadIdx.x;
    mean[t] = g_colsum[t] / (float)nNodes + __ldg(&bl2[t]);
    __syncthreads();
    float s = __ldg(&cb1[t]);
#pragma unroll
    for (int j = 0; j < F; ++j) s = fmaf(mean[j], __ldg(&cw1[t * F + j]), s);
    z[t] = fmaxf(s, 0.f);
    __syncthreads();
    if (t == 0) {
        float o = __ldg(&cb2[0]);
#pragma unroll
        for (int i = 0; i < F; ++i) o = fmaf(z[i], __ldg(&cw2[i]), o);
        outp[0] = 1.f / (1.f + expf(-o));
    }
}

// ---------------------------------------------------------------------------
extern "C" void kernel_launch(void* const* d_in, const int* in_sizes, int n_in,
                              void* d_out, int out_size) {
    const float* x    = (const float*)d_in[0];
    const int*   eidx = (const int*)d_in[1];
    const float* w_l0 = (const float*)d_in[2];
    const float* b_l0 = (const float*)d_in[3];
    const float* w_r0 = (const float*)d_in[4];
    const float* w_l1 = (const float*)d_in[5];
    const float* b_l1 = (const float*)d_in[6];
    const float* w_r1 = (const float*)d_in[7];
    const float* w_l2 = (const float*)d_in[8];
    const float* b_l2 = (const float*)d_in[9];
    const float* w_r2 = (const float*)d_in[10];
    const float* g0   = (const float*)d_in[11];
    const float* be0  = (const float*)d_in[12];
    const float* m0   = (const float*)d_in[13];
    const float* v0   = (const float*)d_in[14];
    const float* g1   = (const float*)d_in[15];
    const float* be1  = (const float*)d_in[16];
    const float* m1   = (const float*)d_in[17];
    const float* v1   = (const float*)d_in[18];
    const float* cw1  = (const float*)d_in[19];
    const float* cb1  = (const float*)d_in[20];
    const float* cw2  = (const float*)d_in[21];
    const float* cb2  = (const float*)d_in[22];
    float* out = (float*)d_out;

    int nN = in_sizes[0] / F;
    int E = in_sizes[1] / 2;
    if (nN > MAXN) nN = MAXN;
    if (E > MAXE) E = MAXE;
    const int* srcp = eidx;
    const int* dstp = eidx + E;

    float *bufA, *bufB;
    cudaGetSymbolAddress((void**)&bufA, g_bufA);
    cudaGetSymbolAddress((void**)&bufB, g_bufB);

    int tb = 256;
    init_kernel<<<(nN + tb - 1) / tb, tb>>>(nN);
    hist_kernel<<<(E + tb - 1) / tb, tb>>>(dstp, E);
    scan_kernel<<<1, 1024>>>(nN);
    scatter_kernel<<<(E + tb - 1) / tb, tb>>>(srcp, dstp, E);

    int aggBlocks = (nN + 7) / 8;           // warp per node, 8 warps/block
    int gemmBlocks = (nN + 255) / 256;

    // Layer 0: x -> bufA
    aggregate_kernel<<<aggBlocks, tb>>>(x, nN);
    gemm_kernel<true><<<gemmBlocks, tb>>>(x, w_l0, w_r0, b_l0, g0, be0, m0, v0,
                                          bufA, nN);
    // Layer 1: bufA -> bufB
    aggregate_kernel<<<aggBlocks, tb>>>(bufA, nN);
    gemm_kernel<true><<<gemmBlocks, tb>>>(bufA, w_l1, w_r1, b_l1, g1, be1, m1,
                                          v1, bufB, nN);
    // Layer 2: bufB -> bufA (no BN/ReLU, bias deferred)
    aggregate_kernel<<<aggBlocks, tb>>>(bufB, nN);
    gemm_kernel<false><<<gemmBlocks, tb>>>(bufB, w_l2, w_r2, b_l2, nullptr,
                                           nullptr, nullptr, nullptr, bufA, nN);

    colsum_kernel<<<256, tb>>>(bufA, nN);
    head_kernel<<<1, F>>>(b_l2, cw1, cb1, cw2, cb2, out, nN);
}

// round 2
// speedup vs baseline: 1.3645x; 1.3645x over previous
#include <cuda_runtime.h>
#include <cuda_bf16.h>
#include <math.h>

// ---------------------------------------------------------------------------
// GraphSAGE fraud detector, fp32.  R2: packed f32x2 GEMM + parallel scan.
// ---------------------------------------------------------------------------

#define MAXN 100000
#define MAXE 1600000
#define F 64

__device__ int   g_deg[MAXN];
__device__ int   g_rowstart[MAXN];
__device__ int   g_cursor[MAXN];
__device__ int   g_srcs[MAXE];
__device__ float g_aggr[(size_t)MAXN * F];
__device__ float g_bufA[(size_t)MAXN * F];
__device__ float g_bufB[(size_t)MAXN * F];
__device__ float g_colsum[F];
__device__ int   g_bsum[256];
__device__ int   g_boff[256];

// ---------------------------------------------------------------------------
__global__ void init_kernel(int nNodes) {
    int i = blockIdx.x * blockDim.x + threadIdx.x;
    if (i < nNodes) g_deg[i] = 0;
    if (i < F) g_colsum[i] = 0.f;
}

__global__ void hist_kernel(const int* __restrict__ dst, int E) {
    int e = blockIdx.x * blockDim.x + threadIdx.x;
    if (e < E) atomicAdd(&g_deg[dst[e]], 1);
}

// --- 3-phase parallel exclusive scan over degrees (2 nodes / thread) -------
__global__ void scan_pass1(int nNodes) {
    int t = threadIdx.x, b = blockIdx.x;
    int base = (b * 256 + t) * 2;
    int s = 0;
    if (base < nNodes) s += g_deg[base];
    if (base + 1 < nNodes) s += g_deg[base + 1];
    __shared__ int sh[256];
    sh[t] = s;
    __syncthreads();
    for (int o = 128; o > 0; o >>= 1) {
        if (t < o) sh[t] += sh[t + o];
        __syncthreads();
    }
    if (t == 0) g_bsum[b] = sh[0];
}

__global__ void scan_pass2() {
    __shared__ int sh[256];
    int t = threadIdx.x;
    int v = g_bsum[t];
    sh[t] = v;
    __syncthreads();
    for (int o = 1; o < 256; o <<= 1) {
        int u = (t >= o) ? sh[t - o] : 0;
        __syncthreads();
        sh[t] += u;
        __syncthreads();
    }
    g_boff[t] = sh[t] - v;
}

__global__ void scan_pass3(int nNodes) {
    int t = threadIdx.x, b = blockIdx.x;
    int base = (b * 256 + t) * 2;
    int d0 = (base < nNodes) ? g_deg[base] : 0;
    int d1 = (base + 1 < nNodes) ? g_deg[base + 1] : 0;
    int s = d0 + d1;
    __shared__ int sh[256];
    sh[t] = s;
    __syncthreads();
    for (int o = 1; o < 256; o <<= 1) {
        int u = (t >= o) ? sh[t - o] : 0;
        __syncthreads();
        sh[t] += u;
        __syncthreads();
    }
    int pre = g_boff[b] + sh[t] - s;
    if (base < nNodes) { g_rowstart[base] = pre; g_cursor[base] = pre; }
    if (base + 1 < nNodes) { g_rowstart[base + 1] = pre + d0; g_cursor[base + 1] = pre + d0; }
}

__global__ void scatter_kernel(const int* __restrict__ src,
                               const int* __restrict__ dst, int E) {
    int e = blockIdx.x * blockDim.x + threadIdx.x;
    if (e < E) {
        int d = dst[e];
        int p = atomicAdd(&g_cursor[d], 1);
        g_srcs[p] = src[e];
    }
}

// ---------------------------------------------------------------------------
// Mean aggregation: one warp per destination node, lane handles 2 features.
__device__ __forceinline__ float2 ld_feat2(const float* __restrict__ h, int s, int lane) {
    return __ldg((const float2*)(h + (size_t)s * F) + lane);
}

__global__ void __launch_bounds__(256) aggregate_kernel(
    const float* __restrict__ hin, int nNodes) {
    int gw = (blockIdx.x * blockDim.x + threadIdx.x) >> 5;
    int lane = threadIdx.x & 31;
    if (gw >= nNodes) return;
    int start = g_rowstart[gw];
    int deg = g_deg[gw];
    float ax = 0.f, ay = 0.f;
    int i = 0;
    for (; i + 4 <= deg; i += 4) {
        int s0 = __ldg(&g_srcs[start + i + 0]);
        int s1 = __ldg(&g_srcs[start + i + 1]);
        int s2 = __ldg(&g_srcs[start + i + 2]);
        int s3 = __ldg(&g_srcs[start + i + 3]);
        float2 t0 = ld_feat2(hin, s0, lane);
        float2 t1 = ld_feat2(hin, s1, lane);
        float2 t2 = ld_feat2(hin, s2, lane);
        float2 t3 = ld_feat2(hin, s3, lane);
        ax += t0.x + t1.x + t2.x + t3.x;
        ay += t0.y + t1.y + t2.y + t3.y;
    }
    for (; i < deg; ++i) {
        int s = __ldg(&g_srcs[start + i]);
        float2 t = ld_feat2(hin, s, lane);
        ax += t.x;
        ay += t.y;
    }
    float inv = deg > 0 ? 1.0f / (float)deg : 0.f;
    ((float2*)(g_aggr + (size_t)gw * F))[lane] = make_float2(ax * inv, ay * inv);
}

// ---------------------------------------------------------------------------
// Fused dual GEMM with packed f32x2 FMA.
// Wt[k][j] = Wl(j,k) for k<64, Wr(j,k-64) for k>=64 (transposed, j contiguous).
// Row stride 68 floats = 272 B (16B-aligned) to dodge transpose-store conflicts.
#define WSTRIDE 68

__device__ __forceinline__ unsigned long long pack2(float v) {
    unsigned int u = __float_as_uint(v);
    unsigned long long r;
    asm("mov.b64 %0, {%1, %1};" : "=l"(r) : "r"(u));
    return r;
}

template <bool BN_RELU>
__global__ void __launch_bounds__(256, 2) gemm_kernel(
    const float* __restrict__ H,
    const float* __restrict__ wl, const float* __restrict__ wr,
    const float* __restrict__ bl,
    const float* __restrict__ gn, const float* __restrict__ be,
    const float* __restrict__ mn, const float* __restrict__ vr,
    float* __restrict__ out, int nNodes) {
    __shared__ __align__(16) float Wt[128][WSTRIDE];
    __shared__ float s_scale[F];
    __shared__ float s_shift[F];

    int tid = threadIdx.x;
    const float4* wl4 = (const float4*)wl;
    const float4* wr4 = (const float4*)wr;
    for (int i = tid; i < 1024; i += 256) {  // 1024 float4 per 64x64 matrix
        int j = i >> 4;          // 0..63  (output col)
        int kc = (i & 15) << 2;  // 0..60  (k chunk)
        float4 a = __ldg(wl4 + i);
        Wt[kc + 0][j] = a.x; Wt[kc + 1][j] = a.y;
        Wt[kc + 2][j] = a.z; Wt[kc + 3][j] = a.w;
        float4 b = __ldg(wr4 + i);
        Wt[64 + kc + 0][j] = b.x; Wt[64 + kc + 1][j] = b.y;
        Wt[64 + kc + 2][j] = b.z; Wt[64 + kc + 3][j] = b.w;
    }
    if (BN_RELU && tid < F) {
        float sc = __ldg(&gn[tid]) * rsqrtf(__ldg(&vr[tid]) + 1e-5f);
        s_scale[tid] = sc;
        s_shift[tid] = (__ldg(&bl[tid]) - __ldg(&mn[tid])) * sc + __ldg(&be[tid]);
    }
    __syncthreads();

    int row = blockIdx.x * 256 + tid;
    if (row >= nNodes) return;

    unsigned long long acc2[32];
#pragma unroll
    for (int j2 = 0; j2 < 32; ++j2) acc2[j2] = 0ull;

    const float4* a4 = (const float4*)(g_aggr + (size_t)row * F);
    const float4* h4 = (const float4*)(H + (size_t)row * F);
#pragma unroll 1
    for (int kk = 0; kk < 8; ++kk) {
        const float4* sp = (kk < 4) ? a4 : h4;
        int base = (kk & 3) * 4;
        float4 v0 = __ldg(sp + base + 0);
        float4 v1 = __ldg(sp + base + 1);
        float4 v2 = __ldg(sp + base + 2);
        float4 v3 = __ldg(sp + base + 3);
        float a[16] = {v0.x, v0.y, v0.z, v0.w, v1.x, v1.y, v1.z, v1.w,
                       v2.x, v2.y, v2.z, v2.w, v3.x, v3.y, v3.z, v3.w};
        int kb = kk * 16;
#pragma unroll
        for (int k = 0; k < 16; ++k) {
            unsigned long long a2 = pack2(a[k]);
            const ulonglong2* wp = (const ulonglong2*)&Wt[kb + k][0];
#pragma unroll
            for (int j4 = 0; j4 < 16; ++j4) {
                ulonglong2 w = wp[j4];
                asm("fma.rn.f32x2 %0, %1, %2, %0;"
                    : "+l"(acc2[2 * j4 + 0]) : "l"(a2), "l"(w.x));
                asm("fma.rn.f32x2 %0, %1, %2, %0;"
                    : "+l"(acc2[2 * j4 + 1]) : "l"(a2), "l"(w.y));
            }
        }
    }

    float o[F];
#pragma unroll
    for (int j2 = 0; j2 < 32; ++j2) {
        unsigned int lo, hi;
        asm("mov.b64 {%0, %1}, %2;" : "=r"(lo), "=r"(hi) : "l"(acc2[j2]));
        float x0 = __uint_as_float(lo);
        float x1 = __uint_as_float(hi);
        if (BN_RELU) {
            x0 = fmaxf(fmaf(x0, s_scale[2 * j2 + 0], s_shift[2 * j2 + 0]), 0.f);
            x1 = fmaxf(fmaf(x1, s_scale[2 * j2 + 1], s_shift[2 * j2 + 1]), 0.f);
        }
        o[2 * j2 + 0] = x0;
        o[2 * j2 + 1] = x1;
    }
    float* orow = out + (size_t)row * F;
#pragma unroll
    for (int j = 0; j < F; j += 4)
        *(float4*)&orow[j] = make_float4(o[j], o[j + 1], o[j + 2], o[j + 3]);
}

// ---------------------------------------------------------------------------
__global__ void colsum_kernel(const float* __restrict__ hin, int nNodes) {
    int t = blockIdx.x * blockDim.x + threadIdx.x;
    int col = t & 63;
    int r = t >> 6;
    int stride = (gridDim.x * blockDim.x) >> 6;
    float s = 0.f;
    for (; r < nNodes; r += stride) s += __ldg(&hin[(size_t)r * F + col]);
    atomicAdd(&g_colsum[col], s);
}

__global__ void head_kernel(const float* __restrict__ bl2,
                            const float* __restrict__ cw1,
                            const float* __restrict__ cb1,
                            const float* __restrict__ cw2,
                            const float* __restrict__ cb2,
                            float* __restrict__ outp, int nNodes) {
    __shared__ float mean[F];
    __shared__ float z[F];
    int t = threadIdx.x;
    mean[t] = g_colsum[t] / (float)nNodes + __ldg(&bl2[t]);
    __syncthreads();
    float s = __ldg(&cb1[t]);
#pragma unroll
    for (int j = 0; j < F; ++j) s = fmaf(mean[j], __ldg(&cw1[t * F + j]), s);
    z[t] = fmaxf(s, 0.f);
    __syncthreads();
    if (t == 0) {
        float o = __ldg(&cb2[0]);
#pragma unroll
        for (int i = 0; i < F; ++i) o = fmaf(z[i], __ldg(&cw2[i]), o);
        outp[0] = 1.f / (1.f + expf(-o));
    }
}

// ---------------------------------------------------------------------------
extern "C" void kernel_launch(void* const* d_in, const int* in_sizes, int n_in,
                              void* d_out, int out_size) {
    const float* x    = (const float*)d_in[0];
    const int*   eidx = (const int*)d_in[1];
    const float* w_l0 = (const float*)d_in[2];
    const float* b_l0 = (const float*)d_in[3];
    const float* w_r0 = (const float*)d_in[4];
    const float* w_l1 = (const float*)d_in[5];
    const float* b_l1 = (const float*)d_in[6];
    const float* w_r1 = (const float*)d_in[7];
    const float* w_l2 = (const float*)d_in[8];
    const float* b_l2 = (const float*)d_in[9];
    const float* w_r2 = (const float*)d_in[10];
    const float* g0   = (const float*)d_in[11];
    const float* be0  = (const float*)d_in[12];
    const float* m0   = (const float*)d_in[13];
    const float* v0   = (const float*)d_in[14];
    const float* g1   = (const float*)d_in[15];
    const float* be1  = (const float*)d_in[16];
    const float* m1   = (const float*)d_in[17];
    const float* v1   = (const float*)d_in[18];
    const float* cw1  = (const float*)d_in[19];
    const float* cb1  = (const float*)d_in[20];
    const float* cw2  = (const float*)d_in[21];
    const float* cb2  = (const float*)d_in[22];
    float* out = (float*)d_out;

    int nN = in_sizes[0] / F;
    int E = in_sizes[1] / 2;
    if (nN > MAXN) nN = MAXN;
    if (E > MAXE) E = MAXE;
    const int* srcp = eidx;
    const int* dstp = eidx + E;

    float *bufA, *bufB;
    cudaGetSymbolAddress((void**)&bufA, g_bufA);
    cudaGetSymbolAddress((void**)&bufB, g_bufB);

    int tb = 256;
    init_kernel<<<(nN + tb - 1) / tb, tb>>>(nN);
    hist_kernel<<<(E + tb - 1) / tb, tb>>>(dstp, E);
    scan_pass1<<<256, 256>>>(nN);
    scan_pass2<<<1, 256>>>();
    scan_pass3<<<256, 256>>>(nN);
    scatter_kernel<<<(E + tb - 1) / tb, tb>>>(srcp, dstp, E);

    int aggBlocks = (nN + 7) / 8;           // warp per node, 8 warps/block
    int gemmBlocks = (nN + 255) / 256;

    // Layer 0: x -> bufA
    aggregate_kernel<<<aggBlocks, tb>>>(x, nN);
    gemm_kernel<true><<<gemmBlocks, tb>>>(x, w_l0, w_r0, b_l0, g0, be0, m0, v0,
                                          bufA, nN);
    // Layer 1: bufA -> bufB
    aggregate_kernel<<<aggBlocks, tb>>>(bufA, nN);
    gemm_kernel<true><<<gemmBlocks, tb>>>(bufA, w_l1, w_r1, b_l1, g1, be1, m1,
                                          v1, bufB, nN);
    // Layer 2: bufB -> bufA (no BN/ReLU, bias deferred to head)
    aggregate_kernel<<<aggBlocks, tb>>>(bufB, nN);
    gemm_kernel<false><<<gemmBlocks, tb>>>(bufB, w_l2, w_r2, b_l2, nullptr,
                                           nullptr, nullptr, nullptr, bufA, nN);

    colsum_kernel<<<256, tb>>>(bufA, nN);
    head_kernel<<<1, F>>>(b_l2, cw1, cb1, cw2, cb2, out, nN);
}